// round 2
// baseline (speedup 1.0000x reference)
#include <cuda_runtime.h>
#include <math.h>
#include <stddef.h>

#define Nh   1024
#define LSEQ 16384
#define NT1  512
#define NT2  32

// ---------------- static device scratch (no allocations allowed) ----------------
__device__ float g_S[Nh*Nh];
__device__ float g_T[Nh*Nh];
__device__ float g_P[Nh*Nh];
__device__ float g_M[Nh*Nh];
__device__ float g_U[NT1*Nh];
__device__ float g_W[NT2*Nh];
__device__ float g_K[LSEQ];

// ---------------- elementwise kernels ----------------
__global__ void k_prep(const float* __restrict__ A, const float* __restrict__ logd,
                       float* __restrict__ S) {
    int i = blockIdx.x*blockDim.x + threadIdx.x;
    float d = (float)exp((double)logd[0]);
    S[i] = 0.5f*d*A[i];
}
__global__ void k_p0(const float* __restrict__ S, const float* __restrict__ T,
                     float* __restrict__ P0) {  // P0 = I + S + S^2
    int i = blockIdx.x*blockDim.x + threadIdx.x;
    float v = S[i] + T[i];
    if ((i>>10) == (i&1023)) v += 1.0f;
    P0[i] = v;
}
__global__ void k_r(const float* __restrict__ P0, const float* __restrict__ T,
                    float* __restrict__ R) {    // R = 2I - P0 + S@P0
    int i = blockIdx.x*blockDim.x + threadIdx.x;
    float v = T[i] - P0[i];
    if ((i>>10) == (i&1023)) v += 2.0f;
    R[i] = v;
}
__global__ void k_mm(const float* __restrict__ P, float* __restrict__ M) { // M = 2P - I
    int i = blockIdx.x*blockDim.x + threadIdx.x;
    float v = 2.0f*P[i];
    if ((i>>10) == (i&1023)) v -= 1.0f;
    M[i] = v;
}
__global__ void k_copy(const float* __restrict__ src, float* __restrict__ dst, int n) {
    int i = blockIdx.x*blockDim.x + threadIdx.x;
    if (i < n) dst[i] = src[i];
}

// ---------------- SGEMM: C(Mrows x 1024) = A(Mrows x 1024) @ B(1024 x 1024) ----------------
// 128x64 CTA tile, BK=16, 256 threads, 8(M)x4(N) micro-tile using packed fma.rn.f32x2
// (pairs along M come free from SMEM; B values duplicated via mov.b64 {r,r}).
#define BM 128
#define BN 64
#define BK 16

__global__ __launch_bounds__(256, 2)
void k_sgemm(const float* __restrict__ A, const float* __restrict__ B,
             float* __restrict__ C, int Mrows) {
    __shared__ float As[BK][BM];   // transposed A tile: As[k][m]
    __shared__ float Bs[BK][BN];
    const int bm = blockIdx.y*BM, bn = blockIdx.x*BN;
    const int tid = threadIdx.x;
    const int tx = tid & 15;       // N: tx*4
    const int ty = tid >> 4;       // M: ty*8

    unsigned long long acc[4][4];
    #pragma unroll
    for (int i = 0; i < 4; i++)
        #pragma unroll
        for (int j = 0; j < 4; j++) acc[i][j] = 0ULL;

    for (int kt = 0; kt < Nh; kt += BK) {
        #pragma unroll
        for (int l = 0; l < 2; l++) {
            int idx = tid + l*256;
            int r = idx >> 2, c4 = (idx & 3) << 2;
            float4 v = make_float4(0.f, 0.f, 0.f, 0.f);
            if (bm + r < Mrows)
                v = *(const float4*)(A + (size_t)(bm + r)*Nh + kt + c4);
            As[c4+0][r] = v.x; As[c4+1][r] = v.y; As[c4+2][r] = v.z; As[c4+3][r] = v.w;
        }
        {
            int r = tid >> 4, c4 = (tid & 15) << 2;
            *(float4*)(&Bs[r][c4]) = *(const float4*)(B + (size_t)(kt + r)*Nh + bn + c4);
        }
        __syncthreads();

        #pragma unroll
        for (int k = 0; k < BK; k++) {
            const unsigned long long* pa =
                (const unsigned long long*)(&As[k][ty*8]);
            unsigned long long a[4];
            a[0] = pa[0]; a[1] = pa[1]; a[2] = pa[2]; a[3] = pa[3];
            float4 bf = *(const float4*)(&Bs[k][tx*4]);
            unsigned long long b[4];
            unsigned int u;
            u = __float_as_uint(bf.x); asm("mov.b64 %0,{%1,%1};" : "=l"(b[0]) : "r"(u));
            u = __float_as_uint(bf.y); asm("mov.b64 %0,{%1,%1};" : "=l"(b[1]) : "r"(u));
            u = __float_as_uint(bf.z); asm("mov.b64 %0,{%1,%1};" : "=l"(b[2]) : "r"(u));
            u = __float_as_uint(bf.w); asm("mov.b64 %0,{%1,%1};" : "=l"(b[3]) : "r"(u));
            #pragma unroll
            for (int i = 0; i < 4; i++)
                #pragma unroll
                for (int j = 0; j < 4; j++)
                    asm("fma.rn.f32x2 %0, %1, %2, %0;"
                        : "+l"(acc[i][j]) : "l"(a[i]), "l"(b[j]));
        }
        __syncthreads();
    }

    #pragma unroll
    for (int i = 0; i < 4; i++) {
        int m0 = bm + ty*8 + 2*i;
        float4 lo, hi;
        lo.x = __uint_as_float((unsigned)(acc[i][0]));  hi.x = __uint_as_float((unsigned)(acc[i][0] >> 32));
        lo.y = __uint_as_float((unsigned)(acc[i][1]));  hi.y = __uint_as_float((unsigned)(acc[i][1] >> 32));
        lo.z = __uint_as_float((unsigned)(acc[i][2]));  hi.z = __uint_as_float((unsigned)(acc[i][2] >> 32));
        lo.w = __uint_as_float((unsigned)(acc[i][3]));  hi.w = __uint_as_float((unsigned)(acc[i][3] >> 32));
        if (m0     < Mrows) *(float4*)(C + (size_t)m0    *Nh + bn + tx*4) = lo;
        if (m0 + 1 < Mrows) *(float4*)(C + (size_t)(m0+1)*Nh + bn + tx*4) = hi;
    }
}

// ---------------- matvec: y = Mat @ x, optional scale by exp(logd) ----------------
__global__ void k_matvec(const float* __restrict__ Mat, const float* __restrict__ x,
                         float* __restrict__ y, const float* __restrict__ logd) {
    int gw   = (blockIdx.x*blockDim.x + threadIdx.x) >> 5;
    int lane = threadIdx.x & 31;
    if (gw >= Nh) return;
    const float4* r  = (const float4*)(Mat + (size_t)gw*Nh);
    const float4* xv = (const float4*)x;
    float acc = 0.f;
    #pragma unroll 4
    for (int j = lane; j < Nh/4; j += 32) {
        float4 a = r[j], b = xv[j];
        acc += a.x*b.x + a.y*b.y + a.z*b.z + a.w*b.w;
    }
    #pragma unroll
    for (int o = 16; o; o >>= 1) acc += __shfl_down_sync(0xffffffffu, acc, o);
    if (lane == 0) {
        float s = 1.f;
        if (logd) s = (float)exp((double)logd[0]);
        y[gw] = s*acc;
    }
}

// ---------------- K[t1 + 512*t2] = dot(U[t1,:], W[t2,:]) ----------------
__global__ void k_gk(const float* __restrict__ U, const float* __restrict__ W,
                     float* __restrict__ K) {
    int gw   = (blockIdx.x*blockDim.x + threadIdx.x) >> 5;
    int lane = threadIdx.x & 31;
    if (gw >= LSEQ) return;
    int t1 = gw & (NT1 - 1);
    int t2 = gw >> 9;
    const float4* u = (const float4*)(U + (size_t)t1*Nh);
    const float4* w = (const float4*)(W + (size_t)t2*Nh);
    float acc = 0.f;
    #pragma unroll 4
    for (int j = lane; j < Nh/4; j += 32) {
        float4 a = u[j], b = w[j];
        acc += a.x*b.x + a.y*b.y + a.z*b.z + a.w*b.w;
    }
    #pragma unroll
    for (int o = 16; o; o >>= 1) acc += __shfl_down_sync(0xffffffffu, acc, o);
    if (lane == 0) K[gw] = acc;
}

// ---------------- causal convolution: Y[k] = sum_{t<=k} K[t] X[k-t] + D*X[k] ----------------
__global__ __launch_bounds__(128)
void k_conv(const float* __restrict__ X, const float* __restrict__ K,
            const float* __restrict__ D, float* __restrict__ Y) {
    __shared__ float Ks[256];
    __shared__ float Xs[128];
    const int i  = blockIdx.x;   // output block
    const int kk = threadIdx.x;
    float acc = 0.f;
    for (int j = 0; j <= i; j++) {
        int base = (i - j) << 7;
        __syncthreads();
        Xs[kk] = X[(j << 7) + kk];
        int i0 = base - 128 + kk;
        Ks[kk]       = (i0 >= 0) ? K[i0] : 0.f;
        Ks[kk + 128] = K[base + kk];
        __syncthreads();
        #pragma unroll 8
        for (int t = 0; t < 128; t++)
            acc += Ks[kk + 128 - t] * Xs[t];
    }
    int k = (i << 7) + kk;
    Y[k] = acc + D[0]*X[k];
}

// ---------------- host ----------------
extern "C" void kernel_launch(void* const* d_in, const int* in_sizes, int n_in,
                              void* d_out, int out_size) {
    // classify inputs by size (dict order: X, A, B, C, D, log_delta)
    int iX=-1, iA=-1, iB=-1, iC=-1, iD=-1, iLd=-1;
    for (int i = 0; i < n_in; i++) {
        int s = in_sizes[i];
        if      (s == Nh*Nh) iA = i;
        else if (s == LSEQ)  iX = i;
        else if (s == Nh)    { if (iB < 0) iB = i; else iC = i; }
        else if (s == 1)     { if (iD < 0) iD = i; else iLd = i; }
    }
    const float* X    = (const float*)d_in[iX];
    const float* A    = (const float*)d_in[iA];
    const float* Bv   = (const float*)d_in[iB];
    const float* Cv   = (const float*)d_in[iC];
    const float* Dv   = (const float*)d_in[iD];
    const float* logd = (const float*)d_in[iLd];
    float* Y = (float*)d_out;
    (void)out_size;

    float *pS, *pT, *pP, *pM, *pU, *pW, *pK;
    cudaGetSymbolAddress((void**)&pS, g_S);
    cudaGetSymbolAddress((void**)&pT, g_T);
    cudaGetSymbolAddress((void**)&pP, g_P);
    cudaGetSymbolAddress((void**)&pM, g_M);
    cudaGetSymbolAddress((void**)&pU, g_U);
    cudaGetSymbolAddress((void**)&pW, g_W);
    cudaGetSymbolAddress((void**)&pK, g_K);

    const int EW = (Nh*Nh)/256;
    dim3 g2(Nh/BN, Nh/BM);   // 16 x 8

    // S = (d/2) A
    k_prep<<<EW, 256>>>(A, logd, pS);
    // P = (I-S)^{-1} via Neumann(2) + Newton:
    k_sgemm<<<g2, 256>>>(pS, pS, pT, Nh);          // T = S^2
    k_p0  <<<EW, 256>>>(pS, pT, pP);               // P0 = I + S + S^2
    k_sgemm<<<g2, 256>>>(pS, pP, pT, Nh);          // T = S@P0
    k_r   <<<EW, 256>>>(pP, pT, pS);               // R = 2I - P0 + S@P0  (into S)
    k_sgemm<<<g2, 256>>>(pP, pS, pT, Nh);          // T = P0@R = A1^{-1}
    k_mm  <<<EW, 256>>>(pT, pM);                   // M = 2P - I  (= dA)
    k_matvec<<<128, 256>>>(pT, Bv, pW, logd);      // W[0] = dB = d * P @ B
    k_copy<<<4, 256>>>(Cv, pU, Nh);                // U[0] = c

    // U doubling with squaring chain: U[2^s..2^{s+1}) = U[0..2^s) @ M^{2^s}
    float* pw   = pM;   // current power M^{2^s}
    float* ping = pT;
    float* pong = pP;
    int rows = 1;
    for (int s = 0; s < 9; s++) {
        dim3 gs(Nh/BN, (rows + BM - 1)/BM);
        k_sgemm<<<gs, 256>>>(pU, pw, pU + (size_t)rows*Nh, rows);
        k_sgemm<<<g2, 256>>>(pw, pw, ping, Nh);    // next power
        pw = ping;
        float* tmp = ping; ping = pong; pong = tmp;
        rows <<= 1;
    }
    // pw now = M^512

    // W[t] = M^512 @ W[t-1], t = 1..31
    for (int t = 1; t < NT2; t++)
        k_matvec<<<128, 256>>>(pw, pW + (size_t)(t-1)*Nh, pW + (size_t)t*Nh, nullptr);

    // K[t1 + 512*t2] = U[t1] . W[t2]
    k_gk<<<LSEQ/8, 256>>>(pU, pW, pK);

    // y = K (*) X + D*X
    k_conv<<<LSEQ/128, 128>>>(X, pK, Dv, Y);
}

// round 3
// speedup vs baseline: 1.3993x; 1.3993x over previous
#include <cuda_runtime.h>
#include <math.h>
#include <stddef.h>

#define Nh   1024
#define LSEQ 16384
#define NT1  512
#define NT2  32

// ---------------- static device scratch ----------------
__device__ float g_S[Nh*Nh];
__device__ float g_T[Nh*Nh];
__device__ float g_P[Nh*Nh];
__device__ float g_M[Nh*Nh];
__device__ float g_U[NT1*Nh];
__device__ float g_W[NT2*Nh];
__device__ float g_K[LSEQ];

// ---------------- elementwise ----------------
__global__ void k_prep(const float* __restrict__ A, const float* __restrict__ logd,
                       float* __restrict__ S) {
    int i = blockIdx.x*blockDim.x + threadIdx.x;
    float d = (float)exp((double)logd[0]);
    S[i] = 0.5f*d*A[i];
}
__global__ void k_p0(const float* __restrict__ S, const float* __restrict__ T,
                     float* __restrict__ P0) {  // P0 = I + S + S^2
    int i = blockIdx.x*blockDim.x + threadIdx.x;
    float v = S[i] + T[i];
    if ((i>>10) == (i&1023)) v += 1.0f;
    P0[i] = v;
}
__global__ void k_r(const float* __restrict__ P0, const float* __restrict__ T,
                    float* __restrict__ R) {    // R = 2I - P0 + S@P0
    int i = blockIdx.x*blockDim.x + threadIdx.x;
    float v = T[i] - P0[i];
    if ((i>>10) == (i&1023)) v += 2.0f;
    R[i] = v;
}
__global__ void k_mm(const float* __restrict__ P, float* __restrict__ M) { // M = 2P - I
    int i = blockIdx.x*blockDim.x + threadIdx.x;
    float v = 2.0f*P[i];
    if ((i>>10) == (i&1023)) v -= 1.0f;
    M[i] = v;
}
__global__ void k_copy(const float* __restrict__ src, float* __restrict__ dst, int n) {
    int i = blockIdx.x*blockDim.x + threadIdx.x;
    if (i < n) dst[i] = src[i];
}

// ---------------- GEMM core: 64x64 tile, BK=16, 256 threads, 4x4 micro (f32x2) ----
#define BM 64
#define BN 64
#define BK 16

__device__ __forceinline__ void gemm_tile(const float* __restrict__ A,
                                          const float* __restrict__ B,
                                          float* __restrict__ C,
                                          int Mrows, int bm, int bn) {
    __shared__ float As[BK][BM];   // transposed: As[k][m]
    __shared__ float Bs[BK][BN];
    const int tid = threadIdx.x;
    const int tx = tid & 15;       // col = tx*4
    const int ty = tid >> 4;       // row = ty*4

    unsigned long long acc[2][4];
    #pragma unroll
    for (int i = 0; i < 2; i++)
        #pragma unroll
        for (int j = 0; j < 4; j++) acc[i][j] = 0ULL;

    // global load indices (one float4 per thread per tile)
    const int ar = tid >> 2, ac4 = (tid & 3) << 2;       // A: 64 rows x 4 quads
    const int br = tid >> 4, bc4 = (tid & 15) << 2;      // B: 16 rows x 16 quads

    for (int kt = 0; kt < Nh; kt += BK) {
        float4 va = make_float4(0.f, 0.f, 0.f, 0.f);
        if (bm + ar < Mrows)
            va = *(const float4*)(A + (size_t)(bm + ar)*Nh + kt + ac4);
        float4 vb = *(const float4*)(B + (size_t)(kt + br)*Nh + bn + bc4);
        As[ac4+0][ar] = va.x; As[ac4+1][ar] = va.y;
        As[ac4+2][ar] = va.z; As[ac4+3][ar] = va.w;
        *(float4*)(&Bs[br][bc4]) = vb;
        __syncthreads();

        #pragma unroll
        for (int k = 0; k < BK; k++) {
            const unsigned long long* pa = (const unsigned long long*)(&As[k][ty*4]);
            unsigned long long a0 = pa[0], a1 = pa[1];
            float4 bf = *(const float4*)(&Bs[k][tx*4]);
            unsigned long long b[4];
            unsigned int u;
            u = __float_as_uint(bf.x); asm("mov.b64 %0,{%1,%1};" : "=l"(b[0]) : "r"(u));
            u = __float_as_uint(bf.y); asm("mov.b64 %0,{%1,%1};" : "=l"(b[1]) : "r"(u));
            u = __float_as_uint(bf.z); asm("mov.b64 %0,{%1,%1};" : "=l"(b[2]) : "r"(u));
            u = __float_as_uint(bf.w); asm("mov.b64 %0,{%1,%1};" : "=l"(b[3]) : "r"(u));
            #pragma unroll
            for (int j = 0; j < 4; j++) {
                asm("fma.rn.f32x2 %0, %1, %2, %0;" : "+l"(acc[0][j]) : "l"(a0), "l"(b[j]));
                asm("fma.rn.f32x2 %0, %1, %2, %0;" : "+l"(acc[1][j]) : "l"(a1), "l"(b[j]));
            }
        }
        __syncthreads();
    }

    #pragma unroll
    for (int i = 0; i < 2; i++) {
        int m0 = bm + ty*4 + 2*i;
        float4 lo, hi;
        lo.x = __uint_as_float((unsigned)(acc[i][0]));  hi.x = __uint_as_float((unsigned)(acc[i][0] >> 32));
        lo.y = __uint_as_float((unsigned)(acc[i][1]));  hi.y = __uint_as_float((unsigned)(acc[i][1] >> 32));
        lo.z = __uint_as_float((unsigned)(acc[i][2]));  hi.z = __uint_as_float((unsigned)(acc[i][2] >> 32));
        lo.w = __uint_as_float((unsigned)(acc[i][3]));  hi.w = __uint_as_float((unsigned)(acc[i][3] >> 32));
        if (m0     < Mrows) *(float4*)(C + (size_t)m0    *Nh + bn + tx*4) = lo;
        if (m0 + 1 < Mrows) *(float4*)(C + (size_t)(m0+1)*Nh + bn + tx*4) = hi;
    }
}

__global__ __launch_bounds__(256)
void k_gemm(const float* __restrict__ A, const float* __restrict__ B,
            float* __restrict__ C, int Mrows) {
    gemm_tile(A, B, C, Mrows, blockIdx.y*BM, blockIdx.x*BN);
}

// Fused doubling step: blocks y<16 do squaring Psq = Pw@Pw,
// blocks y>=16 do U-extension Unext = U[0..rows) @ Pw.
__global__ __launch_bounds__(256)
void k_step(const float* __restrict__ U, const float* __restrict__ Pw,
            float* __restrict__ Unext, int rows, float* __restrict__ Psq) {
    int by = blockIdx.y;
    if (by < 16)
        gemm_tile(Pw, Pw, Psq, Nh, by*BM, blockIdx.x*BN);
    else
        gemm_tile(U, Pw, Unext, rows, (by - 16)*BM, blockIdx.x*BN);
}

// ---------------- matvec: y = Mat @ x, optional scale exp(logd) ----------------
__global__ void k_matvec(const float* __restrict__ Mat, const float* __restrict__ x,
                         float* __restrict__ y, const float* __restrict__ logd) {
    int gw   = (blockIdx.x*blockDim.x + threadIdx.x) >> 5;
    int lane = threadIdx.x & 31;
    if (gw >= Nh) return;
    const float4* r  = (const float4*)(Mat + (size_t)gw*Nh);
    const float4* xv = (const float4*)x;
    float acc = 0.f;
    #pragma unroll 4
    for (int j = lane; j < Nh/4; j += 32) {
        float4 a = r[j], b = xv[j];
        acc += a.x*b.x + a.y*b.y + a.z*b.z + a.w*b.w;
    }
    #pragma unroll
    for (int o = 16; o; o >>= 1) acc += __shfl_down_sync(0xffffffffu, acc, o);
    if (lane == 0) {
        float s = 1.f;
        if (logd) s = (float)exp((double)logd[0]);
        y[gw] = s*acc;
    }
}

// ---------------- K[t1 + 512*t2] = dot(U[t1,:], W[t2,:]) ----------------
__global__ void k_gk(const float* __restrict__ U, const float* __restrict__ W,
                     float* __restrict__ K) {
    int gw   = (blockIdx.x*blockDim.x + threadIdx.x) >> 5;
    int lane = threadIdx.x & 31;
    if (gw >= LSEQ) return;
    int t1 = gw & (NT1 - 1);
    int t2 = gw >> 9;
    const float4* u = (const float4*)(U + (size_t)t1*Nh);
    const float4* w = (const float4*)(W + (size_t)t2*Nh);
    float acc = 0.f;
    #pragma unroll 4
    for (int j = lane; j < Nh/4; j += 32) {
        float4 a = u[j], b = w[j];
        acc += a.x*b.x + a.y*b.y + a.z*b.z + a.w*b.w;
    }
    #pragma unroll
    for (int o = 16; o; o >>= 1) acc += __shfl_down_sync(0xffffffffu, acc, o);
    if (lane == 0) K[gw] = acc;
}

// ---------------- causal conv: Y[k] = sum_{t<=k} K[t] X[k-t] + D*X[k] ----------------
__global__ __launch_bounds__(128)
void k_conv(const float* __restrict__ X, const float* __restrict__ K,
            const float* __restrict__ D, float* __restrict__ Y) {
    __shared__ float Ks[256];
    __shared__ float Xs[128];
    const int i  = blockIdx.x;
    const int kk = threadIdx.x;
    float acc = 0.f;
    for (int j = 0; j <= i; j++) {
        int base = (i - j) << 7;
        __syncthreads();
        Xs[kk] = X[(j << 7) + kk];
        int i0 = base - 128 + kk;
        Ks[kk]       = (i0 >= 0) ? K[i0] : 0.f;
        Ks[kk + 128] = K[base + kk];
        __syncthreads();
        #pragma unroll 8
        for (int t = 0; t < 128; t++)
            acc += Ks[kk + 128 - t] * Xs[t];
    }
    int k = (i << 7) + kk;
    Y[k] = acc + D[0]*X[k];
}

// ---------------- host ----------------
extern "C" void kernel_launch(void* const* d_in, const int* in_sizes, int n_in,
                              void* d_out, int out_size) {
    int iX=-1, iA=-1, iB=-1, iC=-1, iD=-1, iLd=-1;
    for (int i = 0; i < n_in; i++) {
        int s = in_sizes[i];
        if      (s == Nh*Nh) iA = i;
        else if (s == LSEQ)  iX = i;
        else if (s == Nh)    { if (iB < 0) iB = i; else iC = i; }
        else if (s == 1)     { if (iD < 0) iD = i; else iLd = i; }
    }
    const float* X    = (const float*)d_in[iX];
    const float* A    = (const float*)d_in[iA];
    const float* Bv   = (const float*)d_in[iB];
    const float* Cv   = (const float*)d_in[iC];
    const float* Dv   = (const float*)d_in[iD];
    const float* logd = (const float*)d_in[iLd];
    float* Y = (float*)d_out;
    (void)out_size;

    float *pS, *pT, *pP, *pM, *pU, *pW, *pK;
    cudaGetSymbolAddress((void**)&pS, g_S);
    cudaGetSymbolAddress((void**)&pT, g_T);
    cudaGetSymbolAddress((void**)&pP, g_P);
    cudaGetSymbolAddress((void**)&pM, g_M);
    cudaGetSymbolAddress((void**)&pU, g_U);
    cudaGetSymbolAddress((void**)&pW, g_W);
    cudaGetSymbolAddress((void**)&pK, g_K);

    const int EW = (Nh*Nh)/256;
    dim3 g2(Nh/BN, Nh/BM);   // 16 x 16

    // S = (d/2) A ; P = (I-S)^{-1} via Neumann(2) + 1 Newton step
    k_prep<<<EW, 256>>>(A, logd, pS);
    k_gemm<<<g2, 256>>>(pS, pS, pT, Nh);           // T = S^2
    k_p0  <<<EW, 256>>>(pS, pT, pP);               // P0 = I + S + S^2
    k_gemm<<<g2, 256>>>(pS, pP, pT, Nh);           // T = S@P0
    k_r   <<<EW, 256>>>(pP, pT, pS);               // R = 2I - P0 + S@P0
    k_gemm<<<g2, 256>>>(pP, pS, pT, Nh);           // T = P0@R = A1^{-1} = P
    k_mm  <<<EW, 256>>>(pT, pM);                   // M = 2P - I (= dA)
    k_matvec<<<128, 256>>>(pT, Bv, pW, logd);      // W[0] = dB = d * P @ B
    k_copy<<<4, 256>>>(Cv, pU, Nh);                // U[0] = c

    // Fused doubling: U[rows..2rows) = U @ M^{2^s}, and M^{2^{s+1}} = (M^{2^s})^2
    float* pw   = pM;
    float* ping = pT;
    float* pong = pP;
    int rows = 1;
    for (int s = 0; s < 9; s++) {
        int urt = (rows + BM - 1)/BM;
        dim3 gs(Nh/BN, 16 + urt);
        k_step<<<gs, 256>>>(pU, pw, pU + (size_t)rows*Nh, rows, ping);
        pw = ping;
        float* tmp = ping; ping = pong; pong = tmp;
        rows <<= 1;
    }
    // pw = M^512

    // W[t] = M^512 @ W[t-1]
    for (int t = 1; t < NT2; t++)
        k_matvec<<<128, 256>>>(pw, pW + (size_t)(t-1)*Nh, pW + (size_t)t*Nh, nullptr);

    // K[t1 + 512*t2] = U[t1] . W[t2]
    k_gk<<<LSEQ/8, 256>>>(pU, pW, pK);

    // y = K (*) X + D*X
    k_conv<<<LSEQ/128, 128>>>(X, pK, Dv, Y);
}

// round 4
// speedup vs baseline: 1.4231x; 1.0170x over previous
#include <cuda_runtime.h>
#include <math.h>
#include <stddef.h>

#define Nh   1024
#define LSEQ 16384
#define NT1  512
#define NT2  32

// ---------------- static device scratch ----------------
__device__ float g_S[Nh*Nh];
__device__ float g_T[Nh*Nh];
__device__ float g_P[Nh*Nh];
__device__ float g_M[Nh*Nh];
__device__ float g_U[NT1*Nh];
__device__ float g_W[NT2*Nh];
__device__ float g_K[LSEQ];

// ---------------- elementwise ----------------
__global__ void k_prep(const float* __restrict__ A, const float* __restrict__ logd,
                       float* __restrict__ S) {
    int i = blockIdx.x*blockDim.x + threadIdx.x;
    float d = (float)exp((double)logd[0]);
    S[i] = 0.5f*d*A[i];
}
__global__ void k_copy(const float* __restrict__ src, float* __restrict__ dst, int n) {
    int i = blockIdx.x*blockDim.x + threadIdx.x;
    if (i < n) dst[i] = src[i];
}

// ---------------- GEMM: 64x64 tile, BK=32, 256 thr, 4x4 micro (f32x2), double-buffered ----
#define BM 64
#define BN 64
#define BK 32

#define MODE_PLAIN 0
#define MODE_P0    1   // C = I + E + A@B
#define MODE_R     2   // C = 2I - E + A@B
#define MODE_PM    3   // C = A@B ; C2 = 2*(A@B) - I

template<int MODE>
__device__ __forceinline__ void gemm_tile(const float* __restrict__ A,
                                          const float* __restrict__ B,
                                          float* __restrict__ C,
                                          const float* __restrict__ E,
                                          float* __restrict__ C2,
                                          int Mrows, int bm, int bn) {
    __shared__ float As[2][BK][BM];   // transposed: As[buf][k][m]
    __shared__ float Bs[2][BK][BN];
    const int tid = threadIdx.x;
    const int tx = tid & 15;          // out col = tx*4
    const int ty = tid >> 4;          // out row = ty*4

    // load mapping (2 float4 per thread per tile for each of A,B)
    const int ar0 = tid >> 3, ac4 = (tid & 7) << 2;     // A: 64 rows x 8 quads
    const int br0 = tid >> 4, bc4 = (tid & 15) << 2;    // B: 32 rows x 16 quads (rows +0,+16)

    unsigned long long acc[2][4];
    #pragma unroll
    for (int i = 0; i < 2; i++)
        #pragma unroll
        for (int j = 0; j < 4; j++) acc[i][j] = 0ULL;

    float4 na[2], nb[2];
    // prologue: tile 0
    #pragma unroll
    for (int l = 0; l < 2; l++) {
        int r = ar0 + l*32;
        na[l] = make_float4(0.f,0.f,0.f,0.f);
        if (bm + r < Mrows) na[l] = *(const float4*)(A + (size_t)(bm + r)*Nh + ac4);
        nb[l] = *(const float4*)(B + (size_t)(br0 + l*16)*Nh + bn + bc4);
    }
    #pragma unroll
    for (int l = 0; l < 2; l++) {
        int r = ar0 + l*32;
        As[0][ac4+0][r] = na[l].x; As[0][ac4+1][r] = na[l].y;
        As[0][ac4+2][r] = na[l].z; As[0][ac4+3][r] = na[l].w;
        *(float4*)(&Bs[0][br0 + l*16][bc4]) = nb[l];
    }
    __syncthreads();

    const int ntiles = Nh / BK;   // 32
    int buf = 0;
    for (int t = 0; t < ntiles; t++) {
        if (t + 1 < ntiles) {
            int kt = (t + 1) * BK;
            #pragma unroll
            for (int l = 0; l < 2; l++) {
                int r = ar0 + l*32;
                na[l] = make_float4(0.f,0.f,0.f,0.f);
                if (bm + r < Mrows) na[l] = *(const float4*)(A + (size_t)(bm + r)*Nh + kt + ac4);
                nb[l] = *(const float4*)(B + (size_t)(kt + br0 + l*16)*Nh + bn + bc4);
            }
        }
        #pragma unroll
        for (int k = 0; k < BK; k++) {
            ulonglong2 av = *(const ulonglong2*)(&As[buf][k][ty*4]);
            float4 bf = *(const float4*)(&Bs[buf][k][tx*4]);
            unsigned long long b[4];
            unsigned int u;
            u = __float_as_uint(bf.x); asm("mov.b64 %0,{%1,%1};" : "=l"(b[0]) : "r"(u));
            u = __float_as_uint(bf.y); asm("mov.b64 %0,{%1,%1};" : "=l"(b[1]) : "r"(u));
            u = __float_as_uint(bf.z); asm("mov.b64 %0,{%1,%1};" : "=l"(b[2]) : "r"(u));
            u = __float_as_uint(bf.w); asm("mov.b64 %0,{%1,%1};" : "=l"(b[3]) : "r"(u));
            #pragma unroll
            for (int j = 0; j < 4; j++) {
                asm("fma.rn.f32x2 %0, %1, %2, %0;" : "+l"(acc[0][j]) : "l"(av.x), "l"(b[j]));
                asm("fma.rn.f32x2 %0, %1, %2, %0;" : "+l"(acc[1][j]) : "l"(av.y), "l"(b[j]));
            }
        }
        if (t + 1 < ntiles) {
            int nb_buf = buf ^ 1;
            #pragma unroll
            for (int l = 0; l < 2; l++) {
                int r = ar0 + l*32;
                As[nb_buf][ac4+0][r] = na[l].x; As[nb_buf][ac4+1][r] = na[l].y;
                As[nb_buf][ac4+2][r] = na[l].z; As[nb_buf][ac4+3][r] = na[l].w;
                *(float4*)(&Bs[nb_buf][br0 + l*16][bc4]) = nb[l];
            }
        }
        __syncthreads();
        buf ^= 1;
    }

    // epilogue
    #pragma unroll
    for (int i = 0; i < 2; i++) {
        float4 lo, hi;
        lo.x = __uint_as_float((unsigned)(acc[i][0]));  hi.x = __uint_as_float((unsigned)(acc[i][0] >> 32));
        lo.y = __uint_as_float((unsigned)(acc[i][1]));  hi.y = __uint_as_float((unsigned)(acc[i][1] >> 32));
        lo.z = __uint_as_float((unsigned)(acc[i][2]));  hi.z = __uint_as_float((unsigned)(acc[i][2] >> 32));
        lo.w = __uint_as_float((unsigned)(acc[i][3]));  hi.w = __uint_as_float((unsigned)(acc[i][3] >> 32));
        #pragma unroll
        for (int h = 0; h < 2; h++) {
            int m = bm + ty*4 + 2*i + h;
            float4 v = h ? hi : lo;
            int n0 = bn + tx*4;
            if (MODE == MODE_P0 || MODE == MODE_R) {
                float4 e = *(const float4*)(E + (size_t)m*Nh + n0);
                if (MODE == MODE_P0) {
                    v.x += e.x; v.y += e.y; v.z += e.z; v.w += e.w;
                    if (m == n0)   v.x += 1.f; if (m == n0+1) v.y += 1.f;
                    if (m == n0+2) v.z += 1.f; if (m == n0+3) v.w += 1.f;
                } else {
                    v.x -= e.x; v.y -= e.y; v.z -= e.z; v.w -= e.w;
                    if (m == n0)   v.x += 2.f; if (m == n0+1) v.y += 2.f;
                    if (m == n0+2) v.z += 2.f; if (m == n0+3) v.w += 2.f;
                }
            }
            if (MODE == MODE_PLAIN) {
                if (m < Mrows) *(float4*)(C + (size_t)m*Nh + n0) = v;
            } else {
                *(float4*)(C + (size_t)m*Nh + n0) = v;
            }
            if (MODE == MODE_PM) {
                float4 w;
                w.x = 2.f*v.x; w.y = 2.f*v.y; w.z = 2.f*v.z; w.w = 2.f*v.w;
                if (m == n0)   w.x -= 1.f; if (m == n0+1) w.y -= 1.f;
                if (m == n0+2) w.z -= 1.f; if (m == n0+3) w.w -= 1.f;
                *(float4*)(C2 + (size_t)m*Nh + n0) = w;
            }
        }
    }
}

template<int MODE>
__global__ __launch_bounds__(256)
void k_gemm(const float* __restrict__ A, const float* __restrict__ B,
            float* __restrict__ C, const float* __restrict__ E,
            float* __restrict__ C2, int Mrows) {
    gemm_tile<MODE>(A, B, C, E, C2, Mrows, blockIdx.y*BM, blockIdx.x*BN);
}

// Fused doubling step: y<16 -> squaring Psq = Pw@Pw ; y>=16 -> U-ext = U[0..rows)@Pw
__global__ __launch_bounds__(256)
void k_step(const float* __restrict__ U, const float* __restrict__ Pw,
            float* __restrict__ Unext, int rows, float* __restrict__ Psq) {
    int by = blockIdx.y;
    if (by < 16)
        gemm_tile<MODE_PLAIN>(Pw, Pw, Psq, nullptr, nullptr, Nh, by*BM, blockIdx.x*BN);
    else
        gemm_tile<MODE_PLAIN>(U, Pw, Unext, nullptr, nullptr, rows, (by - 16)*BM, blockIdx.x*BN);
}

// ---------------- matvec: y = Mat @ x, optional scale exp(logd) ----------------
__global__ void k_matvec(const float* __restrict__ Mat, const float* __restrict__ x,
                         float* __restrict__ y, const float* __restrict__ logd) {
    int gw   = (blockIdx.x*blockDim.x + threadIdx.x) >> 5;
    int lane = threadIdx.x & 31;
    if (gw >= Nh) return;
    const float4* r  = (const float4*)(Mat + (size_t)gw*Nh);
    const float4* xv = (const float4*)x;
    float acc = 0.f;
    #pragma unroll 4
    for (int j = lane; j < Nh/4; j += 32) {
        float4 a = r[j], b = xv[j];
        acc += a.x*b.x + a.y*b.y + a.z*b.z + a.w*b.w;
    }
    #pragma unroll
    for (int o = 16; o; o >>= 1) acc += __shfl_down_sync(0xffffffffu, acc, o);
    if (lane == 0) {
        float s = 1.f;
        if (logd) s = (float)exp((double)logd[0]);
        y[gw] = s*acc;
    }
}

// ---------------- K[t1 + 512*t2] = dot(U[t1,:], W[t2,:]) ----------------
__global__ void k_gk(const float* __restrict__ U, const float* __restrict__ W,
                     float* __restrict__ K) {
    int gw   = (blockIdx.x*blockDim.x + threadIdx.x) >> 5;
    int lane = threadIdx.x & 31;
    if (gw >= LSEQ) return;
    int t1 = gw & (NT1 - 1);
    int t2 = gw >> 9;
    const float4* u = (const float4*)(U + (size_t)t1*Nh);
    const float4* w = (const float4*)(W + (size_t)t2*Nh);
    float acc = 0.f;
    #pragma unroll 4
    for (int j = lane; j < Nh/4; j += 32) {
        float4 a = u[j], b = w[j];
        acc += a.x*b.x + a.y*b.y + a.z*b.z + a.w*b.w;
    }
    #pragma unroll
    for (int o = 16; o; o >>= 1) acc += __shfl_down_sync(0xffffffffu, acc, o);
    if (lane == 0) K[gw] = acc;
}

// ---------------- causal conv: Y[k] = sum_{t<=k} K[t] X[k-t] + D*X[k] ----------------
__global__ __launch_bounds__(128)
void k_conv(const float* __restrict__ X, const float* __restrict__ K,
            const float* __restrict__ D, float* __restrict__ Y) {
    __shared__ float Ks[256];
    __shared__ float Xs[128];
    const int i  = blockIdx.x;
    const int kk = threadIdx.x;
    float acc = 0.f;
    for (int j = 0; j <= i; j++) {
        int base = (i - j) << 7;
        __syncthreads();
        Xs[kk] = X[(j << 7) + kk];
        int i0 = base - 128 + kk;
        Ks[kk]       = (i0 >= 0) ? K[i0] : 0.f;
        Ks[kk + 128] = K[base + kk];
        __syncthreads();
        #pragma unroll 8
        for (int t = 0; t < 128; t++)
            acc += Ks[kk + 128 - t] * Xs[t];
    }
    int k = (i << 7) + kk;
    Y[k] = acc + D[0]*X[k];
}

// ---------------- host ----------------
extern "C" void kernel_launch(void* const* d_in, const int* in_sizes, int n_in,
                              void* d_out, int out_size) {
    int iX=-1, iA=-1, iB=-1, iC=-1, iD=-1, iLd=-1;
    for (int i = 0; i < n_in; i++) {
        int s = in_sizes[i];
        if      (s == Nh*Nh) iA = i;
        else if (s == LSEQ)  iX = i;
        else if (s == Nh)    { if (iB < 0) iB = i; else iC = i; }
        else if (s == 1)     { if (iD < 0) iD = i; else iLd = i; }
    }
    const float* X    = (const float*)d_in[iX];
    const float* A    = (const float*)d_in[iA];
    const float* Bv   = (const float*)d_in[iB];
    const float* Cv   = (const float*)d_in[iC];
    const float* Dv   = (const float*)d_in[iD];
    const float* logd = (const float*)d_in[iLd];
    float* Y = (float*)d_out;
    (void)out_size;

    float *pS, *pT, *pP, *pM, *pU, *pW, *pK;
    cudaGetSymbolAddress((void**)&pS, g_S);
    cudaGetSymbolAddress((void**)&pT, g_T);
    cudaGetSymbolAddress((void**)&pP, g_P);
    cudaGetSymbolAddress((void**)&pM, g_M);
    cudaGetSymbolAddress((void**)&pU, g_U);
    cudaGetSymbolAddress((void**)&pW, g_W);
    cudaGetSymbolAddress((void**)&pK, g_K);

    const int EW = (Nh*Nh)/256;
    dim3 g2(Nh/BN, Nh/BM);   // 16 x 16

    // S = (d/2) A   -> g_S
    k_prep<<<EW, 256>>>(A, logd, pS);
    // P0 = I + S + S^2                      -> g_P
    k_gemm<MODE_P0><<<g2, 256>>>(pS, pS, pP, pS, nullptr, Nh);
    // R  = 2I - P0 + S@P0                   -> g_T
    k_gemm<MODE_R ><<<g2, 256>>>(pS, pP, pT, pP, nullptr, Nh);
    // P  = P0@R -> g_S ;  M = 2P - I -> g_M
    k_gemm<MODE_PM><<<g2, 256>>>(pP, pT, pS, nullptr, pM, Nh);

    k_matvec<<<128, 256>>>(pS, Bv, pW, logd);      // W[0] = dB = d * P @ B
    k_copy<<<4, 256>>>(Cv, pU, Nh);                // U[0] = c

    // Fused doubling: U[rows..2rows) = U @ M^{2^s}, M^{2^{s+1}} = (M^{2^s})^2
    float* pw   = pM;
    float* ping = pP;
    float* pong = pT;
    int rows = 1;
    for (int s = 0; s < 9; s++) {
        int urt = (rows + BM - 1)/BM;
        dim3 gs(Nh/BN, 16 + urt);
        k_step<<<gs, 256>>>(pU, pw, pU + (size_t)rows*Nh, rows, ping);
        pw = ping;
        float* tmp = ping; ping = pong; pong = tmp;
        rows <<= 1;
    }
    // pw = M^512

    // W[t] = M^512 @ W[t-1]
    for (int t = 1; t < NT2; t++)
        k_matvec<<<128, 256>>>(pw, pW + (size_t)(t-1)*Nh, pW + (size_t)t*Nh, nullptr);

    // K[t1 + 512*t2] = U[t1] . W[t2]
    k_gk<<<LSEQ/8, 256>>>(pU, pW, pK);

    // y = K (*) X + D*X
    k_conv<<<LSEQ/128, 128>>>(X, pK, Dv, Y);
}